// round 1
// baseline (speedup 1.0000x reference)
#include <cuda_runtime.h>
#include <math.h>

#define BB 8
#define QQ 1024
#define KN 1024
#define CC 16
#define OUTD 32
#define HH 16
#define WINDOW 0.25f
#define NTAB 3072
#define CHB 4            // channels per main-kernel block
#define QTHREADS 256

// -------- device scratch (no allocations allowed) --------
__device__ float g_table[CC][NTAB + 1];      // w(a, ch) samples
__device__ float g_pos[BB][KN];              // keys sorted by channel
__device__ float g_val[BB][KN];              // values[b,k,ch_k] sorted by channel
__device__ int   g_seg[BB][CC + 1];          // channel segment offsets
__device__ float g_td[BB][QQ][2 * CC];       // [targets(16) | dens(16)] per (b,q)

// ============================================================
// Kernel 1: tabulate the scalar MLP  w(a, ch) = |MLP(a, onehot(ch))|
// ============================================================
__global__ void build_table_kernel(const float* __restrict__ W0, const float* __restrict__ b0,
                                   const float* __restrict__ W1, const float* __restrict__ b1,
                                   const float* __restrict__ W2, const float* __restrict__ b2,
                                   const float* __restrict__ W3, const float* __restrict__ b3) {
    int i  = blockIdx.x * blockDim.x + threadIdx.x;
    int ch = blockIdx.y;
    if (i > NTAB) return;
    float a = (float)i * (WINDOW / (float)NTAB);

    float h0[HH], h1[HH];
#pragma unroll
    for (int j = 0; j < HH; j++) {
        float v = a * W0[j * (CC + 1)] + W0[j * (CC + 1) + 1 + ch] + b0[j];
        h0[j] = v > 0.0f ? v : 0.0f;
    }
#pragma unroll
    for (int j = 0; j < HH; j++) {
        float s = b1[j];
#pragma unroll
        for (int l = 0; l < HH; l++) s = fmaf(W1[j * HH + l], h0[l], s);
        h1[j] = s > 0.0f ? s : 0.0f;
    }
#pragma unroll
    for (int j = 0; j < HH; j++) {
        float s = b2[j];
#pragma unroll
        for (int l = 0; l < HH; l++) s = fmaf(W2[j * HH + l], h1[l], s);
        h0[j] = s > 0.0f ? s : 0.0f;   // reuse h0 as h2
    }
    float s = b3[0];
#pragma unroll
    for (int l = 0; l < HH; l++) s = fmaf(W3[l], h0[l], s);
    g_table[ch][i] = fabsf(s);
}

// ============================================================
// Kernel 2: counting-sort keys by channel; extract per-key value
// ============================================================
__global__ void sort_keys_kernel(const float* __restrict__ keys_in,
                                 const float* __restrict__ values) {
    int b = blockIdx.x;
    __shared__ int cnt[CC];
    __shared__ int cur[CC];
    int tid = threadIdx.x;
    if (tid < CC) cnt[tid] = 0;
    __syncthreads();
    for (int k = tid; k < KN; k += blockDim.x) {
        int ch = (int)keys_in[(b * KN + k) * 2];
        atomicAdd(&cnt[ch], 1);
    }
    __syncthreads();
    if (tid == 0) {
        int acc = 0;
        for (int c = 0; c < CC; c++) {
            g_seg[b][c] = acc;
            cur[c] = acc;
            acc += cnt[c];
        }
        g_seg[b][CC] = acc;
    }
    __syncthreads();
    for (int k = tid; k < KN; k += blockDim.x) {
        int   ch  = (int)keys_in[(b * KN + k) * 2];
        float pos = keys_in[(b * KN + k) * 2 + 1];
        int r = atomicAdd(&cur[ch], 1);
        g_pos[b][r] = pos;
        g_val[b][r] = values[(b * KN + k) * CC + ch];
    }
}

// ============================================================
// Kernel 3: main pairwise accumulation via table lookup
// grid = (Q/256, 16/CHB, B), block = 256, thread = one query
// ============================================================
__global__ void main_kernel(const float* __restrict__ queries,
                            const float* __restrict__ Wd,
                            const float* __restrict__ bd) {
    extern __shared__ float2 sm[];
    float2* stab = sm;                 // CHB * NTAB duplicated pairs (t[i], t[i+1])
    float2* skey = sm + CHB * NTAB;    // (pos, val) for this channel chunk

    int tid = threadIdx.x;
    int b   = blockIdx.z;
    int c0  = blockIdx.y * CHB;
    int q0  = blockIdx.x * QTHREADS;

    int soff[CHB + 1];
#pragma unroll
    for (int i = 0; i <= CHB; i++) soff[i] = g_seg[b][c0 + i];
    int s0  = soff[0];
    int len = soff[CHB] - s0;

    // stage table chunk into smem as aligned pairs (single LDS.64 lerp source)
#pragma unroll
    for (int cl = 0; cl < CHB; cl++) {
        const float* tb = g_table[c0 + cl];
        for (int i = tid; i < NTAB; i += QTHREADS)
            stab[cl * NTAB + i] = make_float2(tb[i], tb[i + 1]);
    }
    // stage keys of this chunk
    for (int k = tid; k < len; k += QTHREADS)
        skey[k] = make_float2(g_pos[b][s0 + k], g_val[b][s0 + k]);
    __syncthreads();

    float qv  = queries[b * QQ + q0 + tid];
    float wdv = Wd[0];
    float bdv = bd[0];
    const float SCALE = (float)NTAB / WINDOW;
    int qi = q0 + tid;

#pragma unroll
    for (int cl = 0; cl < CHB; cl++) {
        int kb = soff[cl] - s0;
        int ke = soff[cl + 1] - s0;
        const float2* tb = stab + cl * NTAB;
        float den = 0.0f, num = 0.0f;
#pragma unroll 4
        for (int k = kb; k < ke; k++) {
            float2 kv = skey[k];                 // warp-uniform broadcast LDS
            float ad = fabsf(kv.x - qv);         // identical to ref's |pos - q|
            if (ad < WINDOW) {                   // identical strict mask
                float t  = ad * SCALE;
                int   i  = (int)t;
                float fr = t - (float)i;
                float2 tt = tb[i];               // one LDS.64
                float w = fmaf(tt.y - tt.x, fr, tt.x);
                den += w;
                num = fmaf(w, kv.y, num);
            }
        }
        float target = num / (den + 1e-5f);
        float x  = (den * 0.1f - 1.0f) * wdv + bdv;
        float dn = 1.0f / (1.0f + expf(-x));
        g_td[b][qi][c0 + cl]      = target;
        g_td[b][qi][CC + c0 + cl] = dn;
    }
}

// ============================================================
// Kernel 4: epilogue  out = [targets | dens] @ Wr^T + br
// ============================================================
__global__ void epilogue_kernel(const float* __restrict__ Wr,
                                const float* __restrict__ br,
                                float* __restrict__ out) {
    __shared__ float sWr[OUTD * OUTD];
    __shared__ float sbr[OUTD];
    int tid = threadIdx.x;
    for (int i = tid; i < OUTD * OUTD; i += blockDim.x) sWr[i] = Wr[i];
    if (tid < OUTD) sbr[tid] = br[tid];
    __syncthreads();

    int idx = blockIdx.x * blockDim.x + tid;   // flat (b, q)
    if (idx >= BB * QQ) return;
    const float* cat = &g_td[0][0][0] + idx * (2 * CC);

    float acc[OUTD];
#pragma unroll
    for (int o = 0; o < OUTD; o++) acc[o] = sbr[o];
#pragma unroll
    for (int i = 0; i < 2 * CC; i++) {
        float ci = cat[i];
#pragma unroll
        for (int o = 0; o < OUTD; o++)
            acc[o] = fmaf(sWr[o * OUTD + i], ci, acc[o]);
    }
    float* op = out + idx * OUTD;
#pragma unroll
    for (int o = 0; o < OUTD; o++) op[o] = acc[o];
}

// ============================================================
extern "C" void kernel_launch(void* const* d_in, const int* in_sizes, int n_in,
                              void* d_out, int out_size) {
    const float* keys_in = (const float*)d_in[0];
    const float* queries = (const float*)d_in[1];
    const float* values  = (const float*)d_in[2];
    const float* W0 = (const float*)d_in[3];
    const float* b0 = (const float*)d_in[4];
    const float* W1 = (const float*)d_in[5];
    const float* b1 = (const float*)d_in[6];
    const float* W2 = (const float*)d_in[7];
    const float* b2 = (const float*)d_in[8];
    const float* W3 = (const float*)d_in[9];
    const float* b3 = (const float*)d_in[10];
    const float* Wd = (const float*)d_in[11];
    const float* bd = (const float*)d_in[12];
    const float* Wr = (const float*)d_in[13];
    const float* br = (const float*)d_in[14];
    float* out = (float*)d_out;

    const size_t main_smem = (size_t)(CHB * NTAB) * sizeof(float2) + (size_t)KN * sizeof(float2);
    cudaFuncSetAttribute(main_kernel, cudaFuncAttributeMaxDynamicSharedMemorySize,
                         (int)main_smem);

    dim3 tgrid((NTAB + 1 + 255) / 256, CC);
    build_table_kernel<<<tgrid, 256>>>(W0, b0, W1, b1, W2, b2, W3, b3);

    sort_keys_kernel<<<BB, 256>>>(keys_in, values);

    dim3 mgrid(QQ / QTHREADS, CC / CHB, BB);
    main_kernel<<<mgrid, QTHREADS, main_smem>>>(queries, Wd, bd);

    epilogue_kernel<<<(BB * QQ + 255) / 256, 256>>>(Wr, br, out);
}